// round 9
// baseline (speedup 1.0000x reference)
#include <cuda_runtime.h>
#include <cuda_bf16.h>
#include <cstdint>

// CRF log-partition (forward algorithm). B=64, T=2048, C=1, N=128.
//
// 2 independent batches per CTA (grid 32, 256 threads). Each half (4 warps,
// one per SMSP) runs its own forward loop with its OWN named barrier, so the
// two halves drift freely: while one half's warp sits in bar-wait / LDS
// latency / reduce-tree tail, the other half's warp on the same SMSP issues.
// This hides the ~115 cyc/step of exposed latency that bounded the 1-warp/SMSP
// version, at the unchanged HFMA2.BF16 pipe floor (64 HFMA2/thread/step).
//
// Per-half state (scaled-exp domain): alpha_j = m0 + Mint*ln2 + ln(q_j);
// exact power-of-2 renorm keyed on published q0's bf16 exponent.

#define NTAGS 128
#define TMAXR 2048
#define LOG2E_F 1.4426950408889634f

typedef __nv_bfloat16  bf16;
typedef __nv_bfloat162 bf16x2;

__device__ __forceinline__ bf16x2 as_bf2(unsigned u) {
    return *reinterpret_cast<bf16x2*>(&u);
}
__device__ __forceinline__ float ex2(float x) {
    float r;
    asm("ex2.approx.f32 %0, %1;" : "=f"(r) : "f"(x));
    return r;
}
__device__ __forceinline__ void barh(int bid) {           // named barrier, 128 threads
    asm volatile("bar.sync %0, 128;" :: "r"(bid) : "memory");
}

__global__ void __launch_bounds__(256, 1)
crf_logZ_kernel(const float* __restrict__ emissions,    // [B, T, 1, N]
                const int*   __restrict__ token_sizes,  // [B]
                const float* __restrict__ transitions,  // [1,1,N,N] (prev k, next j)
                const float* __restrict__ head_t,       // [N]
                const float* __restrict__ last_t,       // [N]
                float* __restrict__ out)                // [B, 1]
{
    __shared__ __align__(16) bf16 ph[2][2][NTAGS];   // [half][buf][tag]
    __shared__ float redbuf[2][4];

    const int tid  = threadIdx.x;
    const int half = tid >> 7;          // 0 or 1
    const int j    = tid & 127;         // tag index within half
    const int lane = tid & 31;
    const int wh   = (tid >> 5) & 3;    // warp index within half
    const int bid  = 1 + half;          // named barrier id
    const int b    = blockIdx.x * 2 + half;
    const int len  = token_sizes[b];
    const float* emb = emissions + (size_t)b * TMAXR * NTAGS;

    bf16* ph0 = &ph[half][0][0];
    bf16* ph1 = &ph[half][1][0];

    // ---- E column j as 64 bf16x2 pairs over consecutive k (shared by halves) ----
    bf16x2 Eh[NTAGS / 2];
#pragma unroll
    for (int i = 0; i < NTAGS / 2; ++i) {
        float e0 = exp2f(transitions[(2 * i + 0) * NTAGS + j] * LOG2E_F);
        float e1 = exp2f(transitions[(2 * i + 1) * NTAGS + j] * LOG2E_F);
        Eh[i] = __floats2bfloat162_rn(e0, e1);
    }

    // ---- init: alpha0 = head + em[0]; m0 = half-blockmax; q = exp(a0-m0) ----
    float a0 = head_t[j] + emb[j];
    float wm = a0;
#pragma unroll
    for (int o = 16; o > 0; o >>= 1)
        wm = fmaxf(wm, __shfl_xor_sync(0xffffffff, wm, o));
    if (lane == 0) redbuf[half][wh] = wm;
    barh(bid);
    float m0 = fmaxf(fmaxf(redbuf[half][0], redbuf[half][1]),
                     fmaxf(redbuf[half][2], redbuf[half][3]));
    barh(bid);

    bf16 qh   = __float2bfloat16(ex2((a0 - m0) * LOG2E_F));
    int  Mint = 0;

    // ---- emission pipeline: d_c = exp(em[t]) one step early; raw em 3 ahead ----
    float em_a = emb[2 * NTAGS + j];
    float em_b = emb[3 * NTAGS + j];
    float d_c  = ex2(emb[1 * NTAGS + j] * LOG2E_F);

#define STEP(PH, T)                                                          \
    do {                                                                     \
        (PH)[j] = qh;                                                        \
        barh(bid);                                                           \
        unsigned short q0b = *reinterpret_cast<const unsigned short*>(&(PH)[0]); \
        unsigned eh = ((unsigned)q0b >> 7) & 0xffu;                          \
        eh = (eh == 0u) ? 127u : eh;                                         \
        float scale = __uint_as_float((254u - eh) << 23);                    \
        Mint += (int)eh - 127;                                               \
        bf16 hds = __float2bfloat16(d_c * scale);                            \
        const uint4* pv = (const uint4*)(PH);                                \
        bf16x2 s0 = __floats2bfloat162_rn(0.f, 0.f);                         \
        bf16x2 s1 = s0, s2 = s0, s3 = s0;                                    \
        _Pragma("unroll")                                                    \
        for (int i = 0; i < NTAGS / 8; ++i) {                                \
            uint4 v = pv[i];                                                 \
            s0 = __hfma2(as_bf2(v.x), Eh[4 * i + 0], s0);                    \
            s1 = __hfma2(as_bf2(v.y), Eh[4 * i + 1], s1);                    \
            s2 = __hfma2(as_bf2(v.z), Eh[4 * i + 2], s2);                    \
            s3 = __hfma2(as_bf2(v.w), Eh[4 * i + 3], s3);                    \
        }                                                                    \
        int tn = min((T) + 3, TMAXR - 1);                                    \
        float em_f = __ldg(emb + (size_t)tn * NTAGS + j);                    \
        float d_n  = ex2(em_a * LOG2E_F);                                    \
        bf16x2 u0 = __hadd2(s0, s1);                                         \
        bf16x2 u1 = __hadd2(s2, s3);                                         \
        bf16x2 u2 = __hadd2(u0, u1);                                         \
        bf16 sh = __hadd(__low2bfloat16(u2), __high2bfloat16(u2));           \
        qh = __hmul(sh, hds);                                                \
        em_a = em_b; em_b = em_f; d_c = d_n;                                 \
    } while (0)

    int t = 1;
    for (; t + 1 < len; t += 2) {
        STEP(ph0, t);
        STEP(ph1, t + 1);
    }
    if (t < len) {
        STEP(ph0, t);
    }
#undef STEP

    // ---- terminate: out[b] = m0 + Mint*ln2 + ln(sum_j q_j * exp(last_j)) ----
    float v = __bfloat162float(qh) * ex2(last_t[j] * LOG2E_F);
#pragma unroll
    for (int o = 16; o > 0; o >>= 1)
        v += __shfl_xor_sync(0xffffffff, v, o);
    barh(bid);                       // redbuf reuse within half
    if (lane == 0) redbuf[half][wh] = v;
    barh(bid);
    if (j == 0) {
        float sv = (redbuf[half][0] + redbuf[half][1])
                 + (redbuf[half][2] + redbuf[half][3]);
        double r = (double)m0 + (double)Mint * 0.6931471805599453094
                 + log((double)sv);
        out[b] = (float)r;
    }
}

extern "C" void kernel_launch(void* const* d_in, const int* in_sizes, int n_in,
                              void* d_out, int out_size) {
    const float* emissions   = (const float*)d_in[0];  // [64,2048,1,128]
    const int*   token_sizes = (const int*)  d_in[1];  // [64]
    const float* transitions = (const float*)d_in[2];  // [1,1,128,128]
    const float* head_t      = (const float*)d_in[3];  // [1,1,128]
    const float* last_t      = (const float*)d_in[4];  // [1,1,128]
    float* out = (float*)d_out;                        // [64,1]

    crf_logZ_kernel<<<32, 256>>>(emissions, token_sizes, transitions,
                                 head_t, last_t, out);
}

// round 13
// speedup vs baseline: 1.4805x; 1.4805x over previous
#include <cuda_runtime.h>
#include <cuda_bf16.h>
#include <cstdint>

// CRF log-partition via bidirectional (forward-backward) recursion.
// B=64, T=2048, C=1, N=128. One CTA per batch, 256 threads.
//
// Warps 0-3 (group F) run the forward recursion t=1..mid; warps 4-7 (group B)
// run the backward recursion t=len-1..mid. Each group has its own named
// barrier so the two recursions drift freely; each SMSP carries one warp of
// each, hiding the bar/LDS/tail latency that bounds a single recursion
// (R7 measured ~295 cyc per interleaved step-pair vs 2x275 serial).
// Wall iterations per batch: ~len/2.
//
// Both recursions use the exp-domain bf16 machinery: 64 HFMA2.BF16 per
// thread per step, exact power-of-2 renorm keyed on published element 0's
// bf16 exponent, integer exponent accumulator. Combine at the split point:
// logZ = m0 + (Mf+Mb)*ln2 + ln( sum_j qf_j * rb_j ).

#define NTAGS 128
#define TMAXR 2048
#define LOG2E_F 1.4426950408889634f

typedef __nv_bfloat16  bf16;
typedef __nv_bfloat162 bf16x2;

__device__ __forceinline__ bf16x2 as_bf2(unsigned u) {
    return *reinterpret_cast<bf16x2*>(&u);
}
__device__ __forceinline__ float ex2(float x) {
    float r;
    asm("ex2.approx.f32 %0, %1;" : "=f"(r) : "f"(x));
    return r;
}
__device__ __forceinline__ void barh(int bid) {           // named barrier, 128 threads
    asm volatile("bar.sync %0, 128;" :: "r"(bid) : "memory");
}

__global__ void __launch_bounds__(256, 1)
crf_logZ_kernel(const float* __restrict__ emissions,    // [B, T, 1, N]
                const int*   __restrict__ token_sizes,  // [B]
                const float* __restrict__ transitions,  // [1,1,N,N] (prev k, next j)
                const float* __restrict__ head_t,       // [N]
                const float* __restrict__ last_t,       // [N]
                float* __restrict__ out)                // [B, 1]
{
    __shared__ __align__(16) bf16 phf[2][NTAGS];   // forward publish buffers
    __shared__ __align__(16) bf16 phb[2][NTAGS];   // backward publish buffers
    __shared__ float fwd_q[NTAGS];                 // final forward state (fp32)
    __shared__ float bwd_r[NTAGS];                 // final backward state (fp32)
    __shared__ float redbuf[4];
    __shared__ int   mint_s[2];
    __shared__ float m0_s;

    const int tid  = threadIdx.x;
    const int grp  = tid >> 7;          // 0 = forward, 1 = backward
    const int j    = tid & 127;
    const int lane = tid & 31;
    const int wh   = (tid >> 5) & 3;
    const int b    = blockIdx.x;
    const int len  = token_sizes[b];
    const int mid  = len >> 1;          // len >= 1024 per dataset
    const float* emb = emissions + (size_t)b * TMAXR * NTAGS;

    if (grp == 0) {
        // ================= FORWARD: t = 1 .. mid =================
        // E column j: E[k] = exp(trans[k][j]), packed over consecutive k
        bf16x2 Eh[NTAGS / 2];
#pragma unroll
        for (int i = 0; i < NTAGS / 2; ++i) {
            float e0 = exp2f(transitions[(2 * i + 0) * NTAGS + j] * LOG2E_F);
            float e1 = exp2f(transitions[(2 * i + 1) * NTAGS + j] * LOG2E_F);
            Eh[i] = __floats2bfloat162_rn(e0, e1);
        }

        // init: alpha0 = head + em[0]; m0 = group max; q = exp(a0 - m0)
        float a0 = head_t[j] + emb[j];
        float wm = a0;
#pragma unroll
        for (int o = 16; o > 0; o >>= 1)
            wm = fmaxf(wm, __shfl_xor_sync(0xffffffff, wm, o));
        if (lane == 0) redbuf[wh] = wm;
        barh(1);
        float m0 = fmaxf(fmaxf(redbuf[0], redbuf[1]),
                         fmaxf(redbuf[2], redbuf[3]));
        barh(1);

        bf16 qh   = __float2bfloat16(ex2((a0 - m0) * LOG2E_F));
        int  Mint = 0;

        float em_a = emb[2 * NTAGS + j];
        float em_b = emb[3 * NTAGS + j];
        float d_c  = ex2(emb[1 * NTAGS + j] * LOG2E_F);

#define STEPF(PH, T)                                                         \
        do {                                                                 \
            (PH)[j] = qh;                                                    \
            barh(1);                                                         \
            unsigned short q0b = *reinterpret_cast<const unsigned short*>(&(PH)[0]); \
            unsigned eh = ((unsigned)q0b >> 7) & 0xffu;                      \
            eh = (eh == 0u) ? 127u : eh;                                     \
            float scale = __uint_as_float((254u - eh) << 23);                \
            Mint += (int)eh - 127;                                           \
            bf16 hds = __float2bfloat16(d_c * scale);                        \
            const uint4* pv = (const uint4*)(PH);                            \
            bf16x2 s0 = __floats2bfloat162_rn(0.f, 0.f);                     \
            bf16x2 s1 = s0, s2 = s0, s3 = s0;                                \
            _Pragma("unroll")                                                \
            for (int i = 0; i < NTAGS / 8; ++i) {                            \
                uint4 v = pv[i];                                             \
                s0 = __hfma2(as_bf2(v.x), Eh[4 * i + 0], s0);                \
                s1 = __hfma2(as_bf2(v.y), Eh[4 * i + 1], s1);                \
                s2 = __hfma2(as_bf2(v.z), Eh[4 * i + 2], s2);                \
                s3 = __hfma2(as_bf2(v.w), Eh[4 * i + 3], s3);                \
            }                                                                \
            int tn = min((T) + 3, TMAXR - 1);                                \
            float em_f = __ldg(emb + (size_t)tn * NTAGS + j);                \
            float d_n  = ex2(em_a * LOG2E_F);                                \
            bf16x2 u0 = __hadd2(s0, s1);                                     \
            bf16x2 u1 = __hadd2(s2, s3);                                     \
            bf16x2 u2 = __hadd2(u0, u1);                                     \
            bf16 sh = __hadd(__low2bfloat16(u2), __high2bfloat16(u2));       \
            qh = __hmul(sh, hds);                                            \
            em_a = em_b; em_b = em_f; d_c = d_n;                             \
        } while (0)

        int t = 1;
        for (; t + 1 <= mid; t += 2) {
            STEPF(phf[0], t);
            STEPF(phf[1], t + 1);
        }
        if (t <= mid) {
            STEPF(phf[0], t);
        }
#undef STEPF

        fwd_q[j] = __bfloat162float(qh);
        if (j == 0) { mint_s[0] = Mint; m0_s = m0; }
    } else {
        // ================= BACKWARD: t = len-1 .. mid =================
        // E row j: Er[i] = exp(trans[j][2i]), exp(trans[j][2i+1]) packed
        bf16x2 Er[NTAGS / 2];
#pragma unroll
        for (int i = 0; i < NTAGS / 2; ++i) {
            float e0 = exp2f(transitions[j * NTAGS + 2 * i + 0] * LOG2E_F);
            float e1 = exp2f(transitions[j * NTAGS + 2 * i + 1] * LOG2E_F);
            Er[i] = __floats2bfloat162_rn(e0, e1);
        }

        // init: v_{len-1}(j) = exp(last_j + em[len-1][j]); rb init = exp(last)
        float lt  = last_t[j];
        bf16 vh   = __float2bfloat16(ex2((lt + emb[(size_t)(len - 1) * NTAGS + j]) * LOG2E_F));
        bf16 rbh  = __float2bfloat16(ex2(lt * LOG2E_F));
        int  Mint = 0;

        // emission pipeline descending: iteration i targets te = len-2-i,
        // needs d_te. Prefetch 3 ahead (descending), clamped at 0.
        float em_a = emb[(size_t)max(len - 3, 0) * NTAGS + j];
        float em_b = emb[(size_t)max(len - 4, 0) * NTAGS + j];
        float d_c  = ex2(emb[(size_t)max(len - 2, 0) * NTAGS + j] * LOG2E_F);

        const int cnt = len - 1 - mid;   // number of backward matvec steps

#define STEPB(PH, TE)                                                        \
        do {                                                                 \
            (PH)[j] = vh;                                                    \
            barh(2);                                                         \
            unsigned short q0b = *reinterpret_cast<const unsigned short*>(&(PH)[0]); \
            unsigned eh = ((unsigned)q0b >> 7) & 0xffu;                      \
            eh = (eh == 0u) ? 127u : eh;                                     \
            float scale = __uint_as_float((254u - eh) << 23);                \
            Mint += (int)eh - 127;                                           \
            bf16 hsc = __float2bfloat16(scale);                              \
            bf16 hdc = __float2bfloat16(d_c);                                \
            const uint4* pv = (const uint4*)(PH);                            \
            bf16x2 s0 = __floats2bfloat162_rn(0.f, 0.f);                     \
            bf16x2 s1 = s0, s2 = s0, s3 = s0;                                \
            _Pragma("unroll")                                                \
            for (int i = 0; i < NTAGS / 8; ++i) {                            \
                uint4 v = pv[i];                                             \
                s0 = __hfma2(as_bf2(v.x), Er[4 * i + 0], s0);                \
                s1 = __hfma2(as_bf2(v.y), Er[4 * i + 1], s1);                \
                s2 = __hfma2(as_bf2(v.z), Er[4 * i + 2], s2);                \
                s3 = __hfma2(as_bf2(v.w), Er[4 * i + 3], s3);                \
            }                                                                \
            int tn = max((TE) - 3, 0);                                       \
            float em_f = __ldg(emb + (size_t)tn * NTAGS + j);                \
            float d_n  = ex2(em_a * LOG2E_F);                                \
            bf16x2 u0 = __hadd2(s0, s1);                                     \
            bf16x2 u1 = __hadd2(s2, s3);                                     \
            bf16x2 u2 = __hadd2(u0, u1);                                     \
            bf16 sh = __hadd(__low2bfloat16(u2), __high2bfloat16(u2));       \
            rbh = __hmul(sh, hsc);                                           \
            vh  = __hmul(rbh, hdc);                                          \
            em_a = em_b; em_b = em_f; d_c = d_n;                             \
        } while (0)

        int i = 0;
        for (; i + 1 < cnt; i += 2) {
            STEPB(phb[0], len - 2 - i);
            STEPB(phb[1], len - 3 - i);
        }
        if (i < cnt) {
            STEPB(phb[0], len - 2 - i);
        }
#undef STEPB

        bwd_r[j] = __bfloat162float(rbh);
        if (j == 0) mint_s[1] = Mint;
    }

    // ================= combine at t = mid =================
    __syncthreads();
    if (grp == 0) {
        float v = fwd_q[j] * bwd_r[j];
#pragma unroll
        for (int o = 16; o > 0; o >>= 1)
            v += __shfl_xor_sync(0xffffffff, v, o);
        if (lane == 0) redbuf[wh] = v;
        barh(1);
        if (j == 0) {
            float sv = (redbuf[0] + redbuf[1]) + (redbuf[2] + redbuf[3]);
            double r = (double)m0_s
                     + (double)(mint_s[0] + mint_s[1]) * 0.6931471805599453094
                     + log((double)sv);
            out[b] = (float)r;
        }
    }
}

extern "C" void kernel_launch(void* const* d_in, const int* in_sizes, int n_in,
                              void* d_out, int out_size) {
    const float* emissions   = (const float*)d_in[0];  // [64,2048,1,128]
    const int*   token_sizes = (const int*)  d_in[1];  // [64]
    const float* transitions = (const float*)d_in[2];  // [1,1,128,128]
    const float* head_t      = (const float*)d_in[3];  // [1,1,128]
    const float* last_t      = (const float*)d_in[4];  // [1,1,128]
    float* out = (float*)d_out;                        // [64,1]

    crf_logZ_kernel<<<64, 256>>>(emissions, token_sizes, transitions,
                                 head_t, last_t, out);
}

// round 14
// speedup vs baseline: 2.0804x; 1.4052x over previous
#include <cuda_runtime.h>
#include <cuda_bf16.h>
#include <cstdint>

// CRF log-partition via forward-backward split ACROSS CTAs.
// B=64, T=2048, C=1, N=128.
//
// Kernel 1 (grid 128, 128 threads): CTA 2b runs the forward recursion of
// batch b for t=1..mid; CTA 2b+1 runs the backward recursion t=len-1..mid.
// Each CTA is the measured-optimal single-recursion shape (1 warp/SMSP,
// 64 HFMA2.BF16 per thread per step, static double-buffered smem publish,
// exact power-of-2 renorm keyed on published element 0's bf16 exponent).
// Halves deposit their meeting-point state in __device__ scratch.
//
// Kernel 2 (grid 64): logZ_b = m0 + (Mf+Mb)*ln2 + ln(sum_j qf_j * rb_j).

#define NTAGS 128
#define TMAXR 2048
#define LOG2E_F 1.4426950408889634f

typedef __nv_bfloat16  bf16;
typedef __nv_bfloat162 bf16x2;

// cross-kernel scratch (allocation-free)
__device__ float g_fwd[64][NTAGS];
__device__ float g_bwd[64][NTAGS];
__device__ int   g_mint[64][2];
__device__ float g_m0[64];

__device__ __forceinline__ bf16x2 as_bf2(unsigned u) {
    return *reinterpret_cast<bf16x2*>(&u);
}
__device__ __forceinline__ float ex2(float x) {
    float r;
    asm("ex2.approx.f32 %0, %1;" : "=f"(r) : "f"(x));
    return r;
}

__global__ void __launch_bounds__(128, 1)
crf_half_kernel(const float* __restrict__ emissions,    // [B, T, 1, N]
                const int*   __restrict__ token_sizes,  // [B]
                const float* __restrict__ transitions,  // [1,1,N,N] (prev k, next j)
                const float* __restrict__ head_t,       // [N]
                const float* __restrict__ last_t)       // [N]
{
    __shared__ __align__(16) bf16 ph0[NTAGS];
    __shared__ __align__(16) bf16 ph1[NTAGS];
    __shared__ float redbuf[4];

    const int b    = blockIdx.x >> 1;
    const int dir  = blockIdx.x & 1;    // 0 = forward, 1 = backward
    const int j    = threadIdx.x;
    const int lane = j & 31;
    const int warp = j >> 5;
    const int len  = token_sizes[b];
    const int mid  = len >> 1;          // len >= 1024 in this dataset
    const float* emb = emissions + (size_t)b * TMAXR * NTAGS;

    if (dir == 0) {
        // ================= FORWARD: t = 1 .. mid =================
        bf16x2 Eh[NTAGS / 2];
#pragma unroll
        for (int i = 0; i < NTAGS / 2; ++i) {
            float e0 = exp2f(transitions[(2 * i + 0) * NTAGS + j] * LOG2E_F);
            float e1 = exp2f(transitions[(2 * i + 1) * NTAGS + j] * LOG2E_F);
            Eh[i] = __floats2bfloat162_rn(e0, e1);
        }

        float a0 = head_t[j] + emb[j];
        float wm = a0;
#pragma unroll
        for (int o = 16; o > 0; o >>= 1)
            wm = fmaxf(wm, __shfl_xor_sync(0xffffffff, wm, o));
        if (lane == 0) redbuf[warp] = wm;
        __syncthreads();
        float m0 = fmaxf(fmaxf(redbuf[0], redbuf[1]),
                         fmaxf(redbuf[2], redbuf[3]));
        __syncthreads();

        bf16 qh   = __float2bfloat16(ex2((a0 - m0) * LOG2E_F));
        int  Mint = 0;

        float em_a = emb[2 * NTAGS + j];
        float em_b = emb[3 * NTAGS + j];
        float d_c  = ex2(emb[1 * NTAGS + j] * LOG2E_F);

#define STEPF(PH, T)                                                         \
        do {                                                                 \
            (PH)[j] = qh;                                                    \
            __syncthreads();                                                 \
            unsigned short q0b = *reinterpret_cast<const unsigned short*>(&(PH)[0]); \
            unsigned eh = ((unsigned)q0b >> 7) & 0xffu;                      \
            eh = (eh == 0u) ? 127u : eh;                                     \
            float scale = __uint_as_float((254u - eh) << 23);                \
            Mint += (int)eh - 127;                                           \
            bf16 hds = __float2bfloat16(d_c * scale);                        \
            const uint4* pv = (const uint4*)(PH);                            \
            bf16x2 s0 = __floats2bfloat162_rn(0.f, 0.f);                     \
            bf16x2 s1 = s0, s2 = s0, s3 = s0;                                \
            _Pragma("unroll")                                                \
            for (int i = 0; i < NTAGS / 8; ++i) {                            \
                uint4 v = pv[i];                                             \
                s0 = __hfma2(as_bf2(v.x), Eh[4 * i + 0], s0);                \
                s1 = __hfma2(as_bf2(v.y), Eh[4 * i + 1], s1);                \
                s2 = __hfma2(as_bf2(v.z), Eh[4 * i + 2], s2);                \
                s3 = __hfma2(as_bf2(v.w), Eh[4 * i + 3], s3);                \
            }                                                                \
            int tn = min((T) + 3, TMAXR - 1);                                \
            float em_f = __ldg(emb + (size_t)tn * NTAGS + j);                \
            float d_n  = ex2(em_a * LOG2E_F);                                \
            bf16x2 u0 = __hadd2(s0, s1);                                     \
            bf16x2 u1 = __hadd2(s2, s3);                                     \
            bf16x2 u2 = __hadd2(u0, u1);                                     \
            bf16 sh = __hadd(__low2bfloat16(u2), __high2bfloat16(u2));       \
            qh = __hmul(sh, hds);                                            \
            em_a = em_b; em_b = em_f; d_c = d_n;                             \
        } while (0)

        int t = 1;
        for (; t + 1 <= mid; t += 2) {
            STEPF(ph0, t);
            STEPF(ph1, t + 1);
        }
        if (t <= mid) {
            STEPF(ph0, t);
        }
#undef STEPF

        g_fwd[b][j] = __bfloat162float(qh);
        if (j == 0) { g_mint[b][0] = Mint; g_m0[b] = m0; }
    } else {
        // ================= BACKWARD: t = len-1 .. mid =================
        bf16x2 Er[NTAGS / 2];
#pragma unroll
        for (int i = 0; i < NTAGS / 2; ++i) {
            float e0 = exp2f(transitions[j * NTAGS + 2 * i + 0] * LOG2E_F);
            float e1 = exp2f(transitions[j * NTAGS + 2 * i + 1] * LOG2E_F);
            Er[i] = __floats2bfloat162_rn(e0, e1);
        }

        float lt  = last_t[j];
        bf16 vh   = __float2bfloat16(ex2((lt + emb[(size_t)(len - 1) * NTAGS + j]) * LOG2E_F));
        bf16 rbh  = __float2bfloat16(ex2(lt * LOG2E_F));
        int  Mint = 0;

        float em_a = emb[(size_t)max(len - 3, 0) * NTAGS + j];
        float em_b = emb[(size_t)max(len - 4, 0) * NTAGS + j];
        float d_c  = ex2(emb[(size_t)max(len - 2, 0) * NTAGS + j] * LOG2E_F);

        const int cnt = len - 1 - mid;

#define STEPB(PH, TE)                                                        \
        do {                                                                 \
            (PH)[j] = vh;                                                    \
            __syncthreads();                                                 \
            unsigned short q0b = *reinterpret_cast<const unsigned short*>(&(PH)[0]); \
            unsigned eh = ((unsigned)q0b >> 7) & 0xffu;                      \
            eh = (eh == 0u) ? 127u : eh;                                     \
            float scale = __uint_as_float((254u - eh) << 23);                \
            Mint += (int)eh - 127;                                           \
            bf16 hsc = __float2bfloat16(scale);                              \
            bf16 hdc = __float2bfloat16(d_c);                                \
            const uint4* pv = (const uint4*)(PH);                            \
            bf16x2 s0 = __floats2bfloat162_rn(0.f, 0.f);                     \
            bf16x2 s1 = s0, s2 = s0, s3 = s0;                                \
            _Pragma("unroll")                                                \
            for (int i = 0; i < NTAGS / 8; ++i) {                            \
                uint4 v = pv[i];                                             \
                s0 = __hfma2(as_bf2(v.x), Er[4 * i + 0], s0);                \
                s1 = __hfma2(as_bf2(v.y), Er[4 * i + 1], s1);                \
                s2 = __hfma2(as_bf2(v.z), Er[4 * i + 2], s2);                \
                s3 = __hfma2(as_bf2(v.w), Er[4 * i + 3], s3);                \
            }                                                                \
            int tn = max((TE) - 3, 0);                                       \
            float em_f = __ldg(emb + (size_t)tn * NTAGS + j);                \
            float d_n  = ex2(em_a * LOG2E_F);                                \
            bf16x2 u0 = __hadd2(s0, s1);                                     \
            bf16x2 u1 = __hadd2(s2, s3);                                     \
            bf16x2 u2 = __hadd2(u0, u1);                                     \
            bf16 sh = __hadd(__low2bfloat16(u2), __high2bfloat16(u2));       \
            rbh = __hmul(sh, hsc);                                           \
            vh  = __hmul(rbh, hdc);                                          \
            em_a = em_b; em_b = em_f; d_c = d_n;                             \
        } while (0)

        int i = 0;
        for (; i + 1 < cnt; i += 2) {
            STEPB(ph0, len - 2 - i);
            STEPB(ph1, len - 3 - i);
        }
        if (i < cnt) {
            STEPB(ph0, len - 2 - i);
        }
#undef STEPB

        g_bwd[b][j] = __bfloat162float(rbh);
        if (j == 0) g_mint[b][1] = Mint;
    }
}

__global__ void __launch_bounds__(128, 1)
crf_combine_kernel(float* __restrict__ out)             // [B, 1]
{
    __shared__ float redbuf[4];
    const int b    = blockIdx.x;
    const int j    = threadIdx.x;
    const int lane = j & 31;
    const int warp = j >> 5;

    float v = g_fwd[b][j] * g_bwd[b][j];
#pragma unroll
    for (int o = 16; o > 0; o >>= 1)
        v += __shfl_xor_sync(0xffffffff, v, o);
    if (lane == 0) redbuf[warp] = v;
    __syncthreads();
    if (j == 0) {
        float sv = (redbuf[0] + redbuf[1]) + (redbuf[2] + redbuf[3]);
        double r = (double)g_m0[b]
                 + (double)(g_mint[b][0] + g_mint[b][1]) * 0.6931471805599453094
                 + log((double)sv);
        out[b] = (float)r;
    }
}

extern "C" void kernel_launch(void* const* d_in, const int* in_sizes, int n_in,
                              void* d_out, int out_size) {
    const float* emissions   = (const float*)d_in[0];  // [64,2048,1,128]
    const int*   token_sizes = (const int*)  d_in[1];  // [64]
    const float* transitions = (const float*)d_in[2];  // [1,1,128,128]
    const float* head_t      = (const float*)d_in[3];  // [1,1,128]
    const float* last_t      = (const float*)d_in[4];  // [1,1,128]
    float* out = (float*)d_out;                        // [64,1]

    crf_half_kernel<<<128, 128>>>(emissions, token_sizes, transitions,
                                  head_t, last_t);
    crf_combine_kernel<<<64, 128>>>(out);
}

// round 15
// speedup vs baseline: 2.2770x; 1.0945x over previous
#include <cuda_runtime.h>
#include <cuda_bf16.h>
#include <cstdint>

// CRF log-partition via forward-backward split across CTAs, single launch.
// B=64, T=2048, C=1, N=128.
//
// Grid 128 x 128 threads: CTA 2b = forward recursion of batch b (t=1..mid),
// CTA 2b+1 = backward recursion (t=len-1..mid). Per step: 64 HFMA2.BF16 per
// thread with all 16 LDS.128 front-loaded into registers (no LDS-return
// bubbles in the FMA stream); exact power-of-2 renorm keyed on published
// element 0's bf16 exponent; integer exponent accumulator.
//
// The two halves meet through __device__ scratch; a per-batch atomic ticket
// (parity across graph replays, no reset needed) elects the SECOND finisher
// to compute logZ = m0 + (Mf+Mb)*ln2 + ln(sum_j qf_j * rb_j) in-kernel,
// eliminating the separate combine launch.

#define NTAGS 128
#define TMAXR 2048
#define LOG2E_F 1.4426950408889634f

typedef __nv_bfloat16  bf16;
typedef __nv_bfloat162 bf16x2;

__device__ float g_fwd[64][NTAGS];
__device__ float g_bwd[64][NTAGS];
__device__ int   g_mint[64][2];
__device__ float g_m0[64];
__device__ int   g_tick[64];          // monotone ticket; parity selects combiner

__device__ __forceinline__ bf16x2 as_bf2(unsigned u) {
    return *reinterpret_cast<bf16x2*>(&u);
}
__device__ __forceinline__ float ex2(float x) {
    float r;
    asm("ex2.approx.f32 %0, %1;" : "=f"(r) : "f"(x));
    return r;
}

__global__ void __launch_bounds__(128, 1)
crf_half_kernel(const float* __restrict__ emissions,    // [B, T, 1, N]
                const int*   __restrict__ token_sizes,  // [B]
                const float* __restrict__ transitions,  // [1,1,N,N] (prev k, next j)
                const float* __restrict__ head_t,       // [N]
                const float* __restrict__ last_t,       // [N]
                float* __restrict__ out)                // [B, 1]
{
    __shared__ __align__(16) bf16 ph0[NTAGS];
    __shared__ __align__(16) bf16 ph1[NTAGS];
    __shared__ float redbuf[4];
    __shared__ int   tick_s;

    const int b    = blockIdx.x >> 1;
    const int dir  = blockIdx.x & 1;    // 0 = forward, 1 = backward
    const int j    = threadIdx.x;
    const int lane = j & 31;
    const int warp = j >> 5;
    const int len  = token_sizes[b];
    const int mid  = len >> 1;          // len >= 1024 in this dataset
    const float* emb = emissions + (size_t)b * TMAXR * NTAGS;

    if (dir == 0) {
        // ================= FORWARD: t = 1 .. mid =================
        bf16x2 Eh[NTAGS / 2];
#pragma unroll
        for (int i = 0; i < NTAGS / 2; ++i) {
            float e0 = exp2f(transitions[(2 * i + 0) * NTAGS + j] * LOG2E_F);
            float e1 = exp2f(transitions[(2 * i + 1) * NTAGS + j] * LOG2E_F);
            Eh[i] = __floats2bfloat162_rn(e0, e1);
        }

        float a0 = head_t[j] + emb[j];
        float wm = a0;
#pragma unroll
        for (int o = 16; o > 0; o >>= 1)
            wm = fmaxf(wm, __shfl_xor_sync(0xffffffff, wm, o));
        if (lane == 0) redbuf[warp] = wm;
        __syncthreads();
        float m0 = fmaxf(fmaxf(redbuf[0], redbuf[1]),
                         fmaxf(redbuf[2], redbuf[3]));
        __syncthreads();

        bf16 qh   = __float2bfloat16(ex2((a0 - m0) * LOG2E_F));
        int  Mint = 0;

        // emission pipeline: ascending prefetch pointer, clamped offset
        const float* pf = emb + (size_t)4 * NTAGS + j;   // next to fetch (t=4's d src feed)
        const float* pf_end = emb + (size_t)(TMAXR - 1) * NTAGS + j;
        float em_a = emb[2 * NTAGS + j];
        float em_b = emb[3 * NTAGS + j];
        float d_c  = ex2(emb[1 * NTAGS + j] * LOG2E_F);

#define STEPF(PH)                                                            \
        do {                                                                 \
            (PH)[j] = qh;                                                    \
            __syncthreads();                                                 \
            unsigned short q0b = *reinterpret_cast<const unsigned short*>(&(PH)[0]); \
            unsigned eh = ((unsigned)q0b >> 7) & 0xffu;                      \
            eh = (eh == 0u) ? 127u : eh;                                     \
            float scale = __uint_as_float((254u - eh) << 23);                \
            Mint += (int)eh - 127;                                           \
            bf16 hds = __float2bfloat16(d_c * scale);                        \
            const uint4* pv = (const uint4*)(PH);                            \
            uint4 v[16];                                                     \
            _Pragma("unroll")                                                \
            for (int i = 0; i < 16; ++i) v[i] = pv[i];                       \
            bf16x2 s0 = __floats2bfloat162_rn(0.f, 0.f);                     \
            bf16x2 s1 = s0, s2 = s0, s3 = s0;                                \
            _Pragma("unroll")                                                \
            for (int i = 0; i < 16; ++i) {                                   \
                s0 = __hfma2(as_bf2(v[i].x), Eh[4 * i + 0], s0);             \
                s1 = __hfma2(as_bf2(v[i].y), Eh[4 * i + 1], s1);             \
                s2 = __hfma2(as_bf2(v[i].z), Eh[4 * i + 2], s2);             \
                s3 = __hfma2(as_bf2(v[i].w), Eh[4 * i + 3], s3);             \
            }                                                                \
            float em_f = __ldg(pf);                                          \
            pf = (pf < pf_end) ? pf + NTAGS : pf_end;                        \
            float d_n  = ex2(em_a * LOG2E_F);                                \
            bf16x2 u0 = __hadd2(s0, s1);                                     \
            bf16x2 u1 = __hadd2(s2, s3);                                     \
            bf16x2 u2 = __hadd2(u0, u1);                                     \
            bf16 sh = __hadd(__low2bfloat16(u2), __high2bfloat16(u2));       \
            qh = __hmul(sh, hds);                                            \
            em_a = em_b; em_b = em_f; d_c = d_n;                             \
        } while (0)

        int t = 1;
        for (; t + 1 <= mid; t += 2) {
            STEPF(ph0);
            STEPF(ph1);
        }
        if (t <= mid) {
            STEPF(ph0);
        }
#undef STEPF

        g_fwd[b][j] = __bfloat162float(qh);
        if (j == 0) { g_mint[b][0] = Mint; g_m0[b] = m0; }
    } else {
        // ================= BACKWARD: t = len-1 .. mid =================
        bf16x2 Er[NTAGS / 2];
#pragma unroll
        for (int i = 0; i < NTAGS / 2; ++i) {
            float e0 = exp2f(transitions[j * NTAGS + 2 * i + 0] * LOG2E_F);
            float e1 = exp2f(transitions[j * NTAGS + 2 * i + 1] * LOG2E_F);
            Er[i] = __floats2bfloat162_rn(e0, e1);
        }

        float lt  = last_t[j];
        bf16 vh   = __float2bfloat16(ex2((lt + emb[(size_t)(len - 1) * NTAGS + j]) * LOG2E_F));
        bf16 rbh  = __float2bfloat16(ex2(lt * LOG2E_F));
        int  Mint = 0;

        // descending prefetch pointer, clamped at row 0
        const float* pf = emb + (size_t)max(len - 5, 0) * NTAGS + j;
        const float* pf_end = emb + j;
        float em_a = emb[(size_t)max(len - 3, 0) * NTAGS + j];
        float em_b = emb[(size_t)max(len - 4, 0) * NTAGS + j];
        float d_c  = ex2(emb[(size_t)max(len - 2, 0) * NTAGS + j] * LOG2E_F);

        const int cnt = len - 1 - mid;

#define STEPB(PH)                                                            \
        do {                                                                 \
            (PH)[j] = vh;                                                    \
            __syncthreads();                                                 \
            unsigned short q0b = *reinterpret_cast<const unsigned short*>(&(PH)[0]); \
            unsigned eh = ((unsigned)q0b >> 7) & 0xffu;                      \
            eh = (eh == 0u) ? 127u : eh;                                     \
            float scale = __uint_as_float((254u - eh) << 23);                \
            Mint += (int)eh - 127;                                           \
            bf16 hsc = __float2bfloat16(scale);                              \
            bf16 hdc = __float2bfloat16(d_c);                                \
            const uint4* pv = (const uint4*)(PH);                            \
            uint4 v[16];                                                     \
            _Pragma("unroll")                                                \
            for (int i = 0; i < 16; ++i) v[i] = pv[i];                       \
            bf16x2 s0 = __floats2bfloat162_rn(0.f, 0.f);                     \
            bf16x2 s1 = s0, s2 = s0, s3 = s0;                                \
            _Pragma("unroll")                                                \
            for (int i = 0; i < 16; ++i) {                                   \
                s0 = __hfma2(as_bf2(v[i].x), Er[4 * i + 0], s0);             \
                s1 = __hfma2(as_bf2(v[i].y), Er[4 * i + 1], s1);             \
                s2 = __hfma2(as_bf2(v[i].z), Er[4 * i + 2], s2);             \
                s3 = __hfma2(as_bf2(v[i].w), Er[4 * i + 3], s3);             \
            }                                                                \
            float em_f = __ldg(pf);                                          \
            pf = (pf > pf_end) ? pf - NTAGS : pf_end;                        \
            float d_n  = ex2(em_a * LOG2E_F);                                \
            bf16x2 u0 = __hadd2(s0, s1);                                     \
            bf16x2 u1 = __hadd2(s2, s3);                                     \
            bf16x2 u2 = __hadd2(u0, u1);                                     \
            bf16 sh = __hadd(__low2bfloat16(u2), __high2bfloat16(u2));       \
            rbh = __hmul(sh, hsc);                                           \
            vh  = __hmul(rbh, hdc);                                          \
            em_a = em_b; em_b = em_f; d_c = d_n;                             \
        } while (0)

        int i = 0;
        for (; i + 1 < cnt; i += 2) {
            STEPB(ph0);
            STEPB(ph1);
        }
        if (i < cnt) {
            STEPB(ph0);
        }
#undef STEPB

        g_bwd[b][j] = __bfloat162float(rbh);
        if (j == 0) g_mint[b][1] = Mint;
    }

    // ================= in-kernel combine (second finisher) =================
    __syncthreads();
    if (j == 0) {
        __threadfence();                           // publish scratch (release)
        int old = atomicAdd(&g_tick[b], 1);
        tick_s = old;
    }
    __syncthreads();
    if ((tick_s & 1) == 1) {                       // we are the second finisher
        __threadfence();                           // acquire other half's scratch
        float v = g_fwd[b][j] * g_bwd[b][j];
#pragma unroll
        for (int o = 16; o > 0; o >>= 1)
            v += __shfl_xor_sync(0xffffffff, v, o);
        if (lane == 0) redbuf[warp] = v;
        __syncthreads();
        if (j == 0) {
            float sv = (redbuf[0] + redbuf[1]) + (redbuf[2] + redbuf[3]);
            double r = (double)g_m0[b]
                     + (double)(g_mint[b][0] + g_mint[b][1]) * 0.6931471805599453094
                     + log((double)sv);
            out[b] = (float)r;
        }
    }
}

extern "C" void kernel_launch(void* const* d_in, const int* in_sizes, int n_in,
                              void* d_out, int out_size) {
    const float* emissions   = (const float*)d_in[0];  // [64,2048,1,128]
    const int*   token_sizes = (const int*)  d_in[1];  // [64]
    const float* transitions = (const float*)d_in[2];  // [1,1,128,128]
    const float* head_t      = (const float*)d_in[3];  // [1,1,128]
    const float* last_t      = (const float*)d_in[4];  // [1,1,128]
    float* out = (float*)d_out;                        // [64,1]

    crf_half_kernel<<<128, 128>>>(emissions, token_sizes, transitions,
                                  head_t, last_t, out);
}